// round 12
// baseline (speedup 1.0000x reference)
#include <cuda_runtime.h>

// x1:   (16, 1, 224, 224) fp32
// W:    (288, 1, 3, 3)    fp32
// bias: (1, 288, 222, 222) fp32
// out:  (16, 288, 222, 222) fp32 = relu(conv_valid(x1, W) + bias)

#define B_      16
#define COUT_   288
#define HIN_    224
#define WIN_    224
#define HOUT_   222
#define WOUT_   222
#define PLANE_  (HOUT_ * WOUT_)   // 49284
#define ROWS_CTA 6                // 6 output rows per CTA (222 = 37*6)
#define IROWS   (ROWS_CTA + 2)    // 8 input rows
#define NPAIR   111               // float2 pixel pairs per row (222/2)

typedef unsigned long long ull;

// Packed f32x2 ops (sm_103a): one SASS FFMA2 per pixel-pair per tap.
#define FMA2(d, a, b, c) asm("fma.rn.f32x2 %0, %1, %2, %3;" : "=l"(d) : "l"(a), "l"(b), "l"(c))
#define MUL2(d, a, b)    asm("mul.rn.f32x2 %0, %1, %2;"     : "=l"(d) : "l"(a), "l"(b))
#define ADD2(d, a, b)    asm("add.rn.f32x2 %0, %1, %2;"     : "=l"(d) : "l"(a), "l"(b))

__device__ __forceinline__ ull pack2(float lo, float hi) {
    ull r;
    asm("mov.b64 %0, {%1, %2};" : "=l"(r) : "f"(lo), "f"(hi));
    return r;
}
__device__ __forceinline__ void unpack2(float& lo, float& hi, ull v) {
    asm("mov.b64 {%0, %1}, %2;" : "=f"(lo), "=f"(hi) : "l"(v));
}

__global__ __launch_bounds__(256, 4) void conv_bias_relu_kernel(
    const float* __restrict__ x,
    const float* __restrict__ Wt,
    const float* __restrict__ bias,
    float* __restrict__ out)
{
    // Weights stored DUPLICATED: per channel 9 (w,w) pairs padded to 10 doubles
    // (80 B, 16B-aligned). double2 loads yield two lane-duplicated weights each.
    __shared__ __align__(16) float sW[COUT_ * 20];    // 23040 B
    __shared__ __align__(8)  float sIn[IROWS][WIN_];  //  7168 B

    const int hg = blockIdx.x;           // 0..36
    const int b  = blockIdx.y;           // 0..15
    const int t  = threadIdx.x;          // 0..255
    const int h0 = hg * ROWS_CTA;

    // Cooperative weight load with per-lane duplication.
    for (int i = t; i < COUT_ * 9; i += 256) {
        int c = i / 9, j = i - c * 9;
        float w = Wt[i];
        sW[c * 20 + 2 * j]     = w;
        sW[c * 20 + 2 * j + 1] = w;
    }

    // Cooperative load of the 8 input rows (threads 0..223 each take one column).
    const float* xb = x + b * (HIN_ * WIN_);
    if (t < WIN_) {
        #pragma unroll
        for (int r = 0; r < IROWS; r++) sIn[r][t] = xb[(h0 + r) * WIN_ + t];
    }

    __syncthreads();

    // Warp-aligned split: warps 0-3 -> rows h0..h0+2, warps 4-7 -> rows h0+3..h0+5.
    const int half = t >> 7;             // 0 or 1
    const int u    = t & 127;            // pair index; active if < 111
    if (u >= NPAIR) return;

    // Packed tap pairs per input row r: p0=(t0,t1), p1=(t1,t2), p2=(t2,t3)
    // where tk = sIn[row][2u+k]. Built once; invariant over channels.
    ull p[5][3];
    #pragma unroll
    for (int r = 0; r < 5; r++) {
        const float2 a = *reinterpret_cast<const float2*>(&sIn[half * 3 + r][2 * u]);
        const float2 c = *reinterpret_cast<const float2*>(&sIn[half * 3 + r][2 * u + 2]);
        p[r][0] = pack2(a.x, a.y);
        p[r][1] = pack2(a.y, c.x);
        p[r][2] = pack2(c.x, c.y);
    }

    // 32-bit offsets (max tensor 227M elems < 2^31); 2u keeps 8B alignment.
    const int ofs = (h0 + half * 3) * WOUT_ + 2 * u;
    const float* bp = bias + ofs;
    float*       op = out + b * (COUT_ * PLANE_) + ofs;

    const double* sWd = reinterpret_cast<const double*>(sW);

    #pragma unroll 2
    for (int c = 0; c < COUT_; c++) {
        // 4x LDS.128 + 1x LDS.64: ten lane-duplicated weights.
        const double2 wd01 = *reinterpret_cast<const double2*>(sWd + c * 10);
        const double2 wd23 = *reinterpret_cast<const double2*>(sWd + c * 10 + 2);
        const double2 wd45 = *reinterpret_cast<const double2*>(sWd + c * 10 + 4);
        const double2 wd67 = *reinterpret_cast<const double2*>(sWd + c * 10 + 6);
        const double  wd8  = sWd[c * 10 + 8];
        const ull w0 = __double_as_longlong(wd01.x), w1 = __double_as_longlong(wd01.y);
        const ull w2 = __double_as_longlong(wd23.x), w3 = __double_as_longlong(wd23.y);
        const ull w4 = __double_as_longlong(wd45.x), w5 = __double_as_longlong(wd45.y);
        const ull w6 = __double_as_longlong(wd67.x), w7 = __double_as_longlong(wd67.y);
        const ull w8 = __double_as_longlong(wd8);

        #pragma unroll
        for (int r = 0; r < 3; r++) {
            ull y;
            MUL2(y, p[r    ][0], w0);
            FMA2(y, p[r    ][1], w1, y);
            FMA2(y, p[r    ][2], w2, y);
            FMA2(y, p[r + 1][0], w3, y);
            FMA2(y, p[r + 1][1], w4, y);
            FMA2(y, p[r + 1][2], w5, y);
            FMA2(y, p[r + 2][0], w6, y);
            FMA2(y, p[r + 2][1], w7, y);
            FMA2(y, p[r + 2][2], w8, y);

            // Packed bias add (bias row 8B-aligned at this offset), then relu+store.
            const double bv = __ldg(reinterpret_cast<const double*>(bp + r * WOUT_));
            ADD2(y, y, (ull)__double_as_longlong(bv));
            float lo, hi;
            unpack2(lo, hi, y);
            float2 o;
            o.x = fmaxf(lo, 0.0f);
            o.y = fmaxf(hi, 0.0f);
            *reinterpret_cast<float2*>(op + r * WOUT_) = o;
        }
        bp += PLANE_;
        op += PLANE_;
    }
}

extern "C" void kernel_launch(void* const* d_in, const int* in_sizes, int n_in,
                              void* d_out, int out_size)
{
    const float* x    = (const float*)d_in[0];
    const float* Wt   = (const float*)d_in[1];
    const float* bias = (const float*)d_in[2];
    float*       out  = (float*)d_out;

    dim3 grid(HOUT_ / ROWS_CTA, B_);   // 37 x 16 = 592 CTAs
    dim3 block(256);                   // 8 warps, halves warp-aligned
    conv_bias_relu_kernel<<<grid, block>>>(x, Wt, bias, out);
}

// round 13
// speedup vs baseline: 1.2155x; 1.2155x over previous
#include <cuda_runtime.h>

// x1:   (16, 1, 224, 224) fp32
// W:    (288, 1, 3, 3)    fp32
// bias: (1, 288, 222, 222) fp32
// out:  (16, 288, 222, 222) fp32 = relu(conv_valid(x1, W) + bias)

#define B_      16
#define COUT_   288
#define HIN_    224
#define WIN_    224
#define HOUT_   222
#define WOUT_   222
#define PLANE_  (HOUT_ * WOUT_)   // 49284
#define ROWS_CTA 6                // 6 output rows per CTA (222 = 37*6)
#define IROWS   (ROWS_CTA + 2)    // 8 input rows
#define NPAIR   111               // float2 pixel pairs per row (222/2)

__global__ __launch_bounds__(256, 4) void conv_bias_relu_kernel(
    const float* __restrict__ x,
    const float* __restrict__ Wt,
    const float* __restrict__ bias,
    float* __restrict__ out)
{
    // Weights padded to 12 floats/channel: 2x LDS.128 + 1x LDS.32 per channel.
    __shared__ __align__(16) float sW[COUT_ * 12];    // 13824 B
    __shared__ __align__(8)  float sIn[IROWS][WIN_];  //  7168 B

    const int hg = blockIdx.x;           // 0..36
    const int b  = blockIdx.y;           // 0..15
    const int t  = threadIdx.x;          // 0..255
    const int h0 = hg * ROWS_CTA;

    // Cooperative weight load with 9->12 padding.
    for (int i = t; i < COUT_ * 9; i += 256) {
        int c = i / 9, j = i - c * 9;
        sW[c * 12 + j] = Wt[i];
    }

    // Cooperative load of the 8 input rows (threads 0..223 each take one column).
    const float* xb = x + b * (HIN_ * WIN_);
    if (t < WIN_) {
        #pragma unroll
        for (int r = 0; r < IROWS; r++) sIn[r][t] = xb[(h0 + r) * WIN_ + t];
    }

    __syncthreads();

    // Warp-aligned split: warps 0-3 -> rows h0..h0+2, warps 4-7 -> rows h0+3..h0+5.
    const int half = t >> 7;             // 0 or 1
    const int u    = t & 127;            // pair index; active if < 111
    if (u >= NPAIR) return;

    // Taps: 5 input rows x 4 consecutive cols (2u..2u+3), invariant over channels.
    float tap[5][4];
    #pragma unroll
    for (int r = 0; r < 5; r++) {
        float2 a = *reinterpret_cast<const float2*>(&sIn[half * 3 + r][2 * u]);
        float2 c = *reinterpret_cast<const float2*>(&sIn[half * 3 + r][2 * u + 2]);
        tap[r][0] = a.x; tap[r][1] = a.y; tap[r][2] = c.x; tap[r][3] = c.y;
    }

    // 32-bit offsets (max tensor 227M elems < 2^31).
    const int ofs = (h0 + half * 3) * WOUT_ + 2 * u;          // 8B aligned
    const float* bp = bias + ofs;
    float*       op = out + b * (COUT_ * PLANE_) + ofs;

    // Bias prefetch, one full channel ahead (removes LDG->ADD serialization).
    float2 bnx[3];
    #pragma unroll
    for (int r = 0; r < 3; r++)
        bnx[r] = __ldg(reinterpret_cast<const float2*>(bp + r * WOUT_));

    #pragma unroll 2
    for (int c = 0; c < COUT_; c++) {
        const float4 wA = *reinterpret_cast<const float4*>(&sW[c * 12]);     // w0..w3
        const float4 wB = *reinterpret_cast<const float4*>(&sW[c * 12 + 4]); // w4..w7
        const float  w8 = sW[c * 12 + 8];

        float2 bcur[3];
        #pragma unroll
        for (int r = 0; r < 3; r++) bcur[r] = bnx[r];
        if (c + 1 < COUT_) {
            bp += PLANE_;
            #pragma unroll
            for (int r = 0; r < 3; r++)
                bnx[r] = __ldg(reinterpret_cast<const float2*>(bp + r * WOUT_));
        }

        #pragma unroll
        for (int r = 0; r < 3; r++) {
            // Two parallel partial chains per pixel: depth 5 + depth 4, then join.
            float a0, b0, a1, b1;
            a0 = tap[r  ][0] * wA.x;             a1 = tap[r  ][1] * wA.x;
            b0 = tap[r  ][1] * wA.y;             b1 = tap[r  ][2] * wA.y;
            a0 = fmaf(tap[r  ][2], wA.z, a0);    a1 = fmaf(tap[r  ][3], wA.z, a1);
            b0 = fmaf(tap[r+1][0], wA.w, b0);    b1 = fmaf(tap[r+1][1], wA.w, b1);
            a0 = fmaf(tap[r+1][1], wB.x, a0);    a1 = fmaf(tap[r+1][2], wB.x, a1);
            b0 = fmaf(tap[r+1][2], wB.y, b0);    b1 = fmaf(tap[r+1][3], wB.y, b1);
            a0 = fmaf(tap[r+2][0], wB.z, a0);    a1 = fmaf(tap[r+2][1], wB.z, a1);
            b0 = fmaf(tap[r+2][1], wB.w, b0);    b1 = fmaf(tap[r+2][2], wB.w, b1);
            a0 = fmaf(tap[r+2][2], w8,  a0);     a1 = fmaf(tap[r+2][3], w8,  a1);
            // join + bias (bias folded into the b-chain join)
            b0 += bcur[r].x;                     b1 += bcur[r].y;
            float2 o;
            o.x = fmaxf(a0 + b0, 0.0f);
            o.y = fmaxf(a1 + b1, 0.0f);
            *reinterpret_cast<float2*>(op + r * WOUT_) = o;
        }
        op += PLANE_;
    }
}

extern "C" void kernel_launch(void* const* d_in, const int* in_sizes, int n_in,
                              void* d_out, int out_size)
{
    const float* x    = (const float*)d_in[0];
    const float* Wt   = (const float*)d_in[1];
    const float* bias = (const float*)d_in[2];
    float*       out  = (float*)d_out;

    dim3 grid(HOUT_ / ROWS_CTA, B_);   // 37 x 16 = 592 CTAs
    dim3 block(256);                   // 8 warps, halves warp-aligned
    conv_bias_relu_kernel<<<grid, block>>>(x, Wt, bias, out);
}

// round 14
// speedup vs baseline: 1.2500x; 1.0284x over previous
#include <cuda_runtime.h>

// x1:   (16, 1, 224, 224) fp32
// W:    (288, 1, 3, 3)    fp32
// bias: (1, 288, 222, 222) fp32
// out:  (16, 288, 222, 222) fp32 = relu(conv_valid(x1, W) + bias)

#define B_      16
#define COUT_   288
#define HIN_    224
#define WIN_    224
#define HOUT_   222
#define WOUT_   222
#define PLANE_  (HOUT_ * WOUT_)   // 49284
#define ROWS_CTA 6                // 6 output rows per CTA (222 = 37*6)
#define IROWS   (ROWS_CTA + 2)    // 8 input rows
#define NPAIR   111               // float2 pixel pairs per row (222/2)

__global__ __launch_bounds__(256, 4) void conv_bias_relu_kernel(
    const float* __restrict__ x,
    const float* __restrict__ Wt,
    const float* __restrict__ bias,
    float* __restrict__ out)
{
    // Weights padded to 12 floats/channel: 2x LDS.128 + 1x LDS.32 per channel.
    __shared__ __align__(16) float sW[COUT_ * 12];    // 13824 B
    __shared__ __align__(8)  float sIn[IROWS][WIN_];  //  7168 B

    const int hg = blockIdx.x;           // 0..36
    const int b  = blockIdx.y;           // 0..15
    const int t  = threadIdx.x;          // 0..255
    const int h0 = hg * ROWS_CTA;

    // Cooperative weight load with 9->12 padding.
    for (int i = t; i < COUT_ * 9; i += 256) {
        int c = i / 9, j = i - c * 9;
        sW[c * 12 + j] = Wt[i];
    }

    // Cooperative load of the 8 input rows (threads 0..223 each take one column).
    const float* xb = x + b * (HIN_ * WIN_);
    if (t < WIN_) {
        #pragma unroll
        for (int r = 0; r < IROWS; r++) sIn[r][t] = xb[(h0 + r) * WIN_ + t];
    }

    __syncthreads();

    // Warp-aligned split: warps 0-3 -> rows h0..h0+2, warps 4-7 -> rows h0+3..h0+5.
    const int half = t >> 7;             // 0 or 1
    const int u    = t & 127;            // pair index; active if < 111
    if (u >= NPAIR) return;

    // Taps: 5 input rows x 4 consecutive cols (2u..2u+3), invariant over channels.
    float tap[5][4];
    #pragma unroll
    for (int r = 0; r < 5; r++) {
        float2 a = *reinterpret_cast<const float2*>(&sIn[half * 3 + r][2 * u]);
        float2 c = *reinterpret_cast<const float2*>(&sIn[half * 3 + r][2 * u + 2]);
        tap[r][0] = a.x; tap[r][1] = a.y; tap[r][2] = c.x; tap[r][3] = c.y;
    }

    // 32-bit offsets (max tensor 227M elems < 2^31).
    const int ofs = (h0 + half * 3) * WOUT_ + 2 * u;          // 8B aligned
    const float* bp = bias + ofs;
    float*       op = out + b * (COUT_ * PLANE_) + ofs;

    #pragma unroll 2
    for (int c = 0; c < COUT_; c++) {
        const float4 wA = *reinterpret_cast<const float4*>(&sW[c * 12]);     // w0..w3
        const float4 wB = *reinterpret_cast<const float4*>(&sW[c * 12 + 4]); // w4..w7
        const float  w8 = sW[c * 12 + 8];

        #pragma unroll
        for (int r = 0; r < 3; r++) {
            float y0, y1;
            y0 = tap[r][0] * wA.x;               y1 = tap[r][1] * wA.x;
            y0 = fmaf(tap[r][1], wA.y, y0);      y1 = fmaf(tap[r][2], wA.y, y1);
            y0 = fmaf(tap[r][2], wA.z, y0);      y1 = fmaf(tap[r][3], wA.z, y1);
            y0 = fmaf(tap[r+1][0], wA.w, y0);    y1 = fmaf(tap[r+1][1], wA.w, y1);
            y0 = fmaf(tap[r+1][1], wB.x, y0);    y1 = fmaf(tap[r+1][2], wB.x, y1);
            y0 = fmaf(tap[r+1][2], wB.y, y0);    y1 = fmaf(tap[r+1][3], wB.y, y1);
            y0 = fmaf(tap[r+2][0], wB.z, y0);    y1 = fmaf(tap[r+2][1], wB.z, y1);
            y0 = fmaf(tap[r+2][1], wB.w, y0);    y1 = fmaf(tap[r+2][2], wB.w, y1);
            y0 = fmaf(tap[r+2][2], w8,  y0);     y1 = fmaf(tap[r+2][3], w8,  y1);

            const float2 bv = __ldg(reinterpret_cast<const float2*>(bp + r * WOUT_));
            float2 o;
            o.x = fmaxf(y0 + bv.x, 0.0f);
            o.y = fmaxf(y1 + bv.y, 0.0f);
            // Write-through streaming store: output is never re-read; skip L2 retention.
            __stwt(reinterpret_cast<float2*>(op + r * WOUT_), o);
        }
        bp += PLANE_;
        op += PLANE_;
    }
}

extern "C" void kernel_launch(void* const* d_in, const int* in_sizes, int n_in,
                              void* d_out, int out_size)
{
    const float* x    = (const float*)d_in[0];
    const float* Wt   = (const float*)d_in[1];
    const float* bias = (const float*)d_in[2];
    float*       out  = (float*)d_out;

    dim3 grid(HOUT_ / ROWS_CTA, B_);   // 37 x 16 = 592 CTAs
    dim3 block(256);                   // 8 warps, halves warp-aligned
    conv_bias_relu_kernel<<<grid, block>>>(x, Wt, bias, out);
}

// round 15
// speedup vs baseline: 1.2606x; 1.0085x over previous
#include <cuda_runtime.h>

// x1:   (16, 1, 224, 224) fp32
// W:    (288, 1, 3, 3)    fp32
// bias: (1, 288, 222, 222) fp32
// out:  (16, 288, 222, 222) fp32 = relu(conv_valid(x1, W) + bias)

#define B_      16
#define COUT_   288
#define HIN_    224
#define WIN_    224
#define HOUT_   222
#define WOUT_   222
#define PLANE_  (HOUT_ * WOUT_)   // 49284
#define ROWS_CTA 2                // 2 output rows per CTA (222 = 111*2)
#define IROWS   (ROWS_CTA + 2)    // 4 input rows
#define NBATCH  2                 // batches per CTA (bias reused in registers)
#define NPAIR   111               // float2 pixel pairs per row

__global__ __launch_bounds__(128, 6) void conv_bias_relu_kernel(
    const float* __restrict__ x,
    const float* __restrict__ Wt,
    const float* __restrict__ bias,
    float* __restrict__ out)
{
    // Weights padded to 12 floats/channel: 2x LDS.128 + 1x LDS.32 per channel.
    __shared__ __align__(16) float sW[COUT_ * 12];            // 13824 B
    __shared__ __align__(8)  float sIn[NBATCH][IROWS][WIN_];  //  7168 B

    const int hg = blockIdx.x;            // 0..110 (row group)
    const int bg = blockIdx.y;            // 0..7   (batch pair)
    const int t  = threadIdx.x;           // 0..127
    const int h0 = hg * ROWS_CTA;
    const int b0 = bg * NBATCH;

    // Cooperative weight load with 9->12 padding.
    for (int i = t; i < COUT_ * 9; i += 128) {
        int c = i / 9, j = i - c * 9;
        sW[c * 12 + j] = Wt[i];
    }

    // Cooperative load: 2 batches x 4 input rows x 224 cols.
    for (int i = t; i < NBATCH * IROWS * WIN_; i += 128) {
        int bb = i / (IROWS * WIN_);
        int rem = i - bb * (IROWS * WIN_);
        int r = rem / WIN_, w = rem - r * WIN_;
        sIn[bb][r][w] = x[(b0 + bb) * (HIN_ * WIN_) + (h0 + r) * WIN_ + w];
    }

    __syncthreads();

    if (t >= NPAIR) return;   // 111 active pair-threads

    // Taps: 2 batches x 4 rows x 4 consecutive cols (2t..2t+3). 32 registers.
    float tap[NBATCH][IROWS][4];
    #pragma unroll
    for (int bb = 0; bb < NBATCH; bb++) {
        #pragma unroll
        for (int r = 0; r < IROWS; r++) {
            float2 a = *reinterpret_cast<const float2*>(&sIn[bb][r][2 * t]);
            float2 c = *reinterpret_cast<const float2*>(&sIn[bb][r][2 * t + 2]);
            tap[bb][r][0] = a.x; tap[bb][r][1] = a.y;
            tap[bb][r][2] = c.x; tap[bb][r][3] = c.y;
        }
    }

    // 32-bit offsets (max 227M elems < 2^31); 2t keeps 8B alignment.
    const int ofs = h0 * WOUT_ + 2 * t;
    const float* bp  = bias + ofs;
    float*       op0 = out + (b0    ) * (COUT_ * PLANE_) + ofs;
    float*       op1 = out + (b0 + 1) * (COUT_ * PLANE_) + ofs;

    #pragma unroll 2
    for (int c = 0; c < COUT_; c++) {
        const float4 wA = *reinterpret_cast<const float4*>(&sW[c * 12]);     // w0..w3
        const float4 wB = *reinterpret_cast<const float4*>(&sW[c * 12 + 4]); // w4..w7
        const float  w8 = sW[c * 12 + 8];

        // Bias loaded ONCE per channel, reused for both batches (registers).
        float2 bv[ROWS_CTA];
        #pragma unroll
        for (int r = 0; r < ROWS_CTA; r++)
            bv[r] = __ldg(reinterpret_cast<const float2*>(bp + r * WOUT_));

        #pragma unroll
        for (int bb = 0; bb < NBATCH; bb++) {
            float* op = bb ? op1 : op0;
            #pragma unroll
            for (int r = 0; r < ROWS_CTA; r++) {
                float y0, y1;
                y0 = tap[bb][r][0] * wA.x;              y1 = tap[bb][r][1] * wA.x;
                y0 = fmaf(tap[bb][r][1],   wA.y, y0);   y1 = fmaf(tap[bb][r][2],   wA.y, y1);
                y0 = fmaf(tap[bb][r][2],   wA.z, y0);   y1 = fmaf(tap[bb][r][3],   wA.z, y1);
                y0 = fmaf(tap[bb][r+1][0], wA.w, y0);   y1 = fmaf(tap[bb][r+1][1], wA.w, y1);
                y0 = fmaf(tap[bb][r+1][1], wB.x, y0);   y1 = fmaf(tap[bb][r+1][2], wB.x, y1);
                y0 = fmaf(tap[bb][r+1][2], wB.y, y0);   y1 = fmaf(tap[bb][r+1][3], wB.y, y1);
                y0 = fmaf(tap[bb][r+2][0], wB.z, y0);   y1 = fmaf(tap[bb][r+2][1], wB.z, y1);
                y0 = fmaf(tap[bb][r+2][1], wB.w, y0);   y1 = fmaf(tap[bb][r+2][2], wB.w, y1);
                y0 = fmaf(tap[bb][r+2][2], w8,   y0);   y1 = fmaf(tap[bb][r+2][3], w8,   y1);

                float2 o;
                o.x = fmaxf(y0 + bv[r].x, 0.0f);
                o.y = fmaxf(y1 + bv[r].y, 0.0f);
                *reinterpret_cast<float2*>(op + r * WOUT_) = o;
            }
        }
        bp  += PLANE_;
        op0 += PLANE_;
        op1 += PLANE_;
    }
}

extern "C" void kernel_launch(void* const* d_in, const int* in_sizes, int n_in,
                              void* d_out, int out_size)
{
    const float* x    = (const float*)d_in[0];
    const float* Wt   = (const float*)d_in[1];
    const float* bias = (const float*)d_in[2];
    float*       out  = (float*)d_out;

    dim3 grid(HOUT_ / ROWS_CTA, B_ / NBATCH);   // 111 x 8 = 888 CTAs (6/SM)
    dim3 block(128);                            // 4 warps, 111 active pair-threads
    conv_bias_relu_kernel<<<grid, block>>>(x, Wt, bias, out);
}